// round 3
// baseline (speedup 1.0000x reference)
#include <cuda_runtime.h>
#include <cstddef>

// ---------------------------------------------------------------------------
// ComplexSpatialAttentionModule: B=4, C=256, H=W=64 (N=4096 tokens), DQK=32.
//   q = wq@x+bq  [B,32,N]; k = wk@x+bk [B,32,N]; v = wv@x+bv [B,256,N]
//   attn = softmax_n(q^T k);  O[b,c,m] = sum_n v[b,c,n] attn[m,n]
//   out  = wo@O + bo + x
// Two-pass (recompute-QK) streaming softmax. All inner loops use packed
// fma.rn.f32x2 (2 FLOP/issue; ptxas never emits it from C++).
// ---------------------------------------------------------------------------

#define BATCH 4
#define CCH   256
#define DQK   32
#define NTOK  4096
#define BM    64
#define BN    64
#define PT_S  (BM + 4)    // padded stride for p^T tile
#define VT_S  (CCH + 4)   // padded stride for v^T tile

typedef unsigned long long u64t;

// d = a * b + c, elementwise on packed f32x2
#define FMA2(d, a, b, c) \
    asm("fma.rn.f32x2 %0, %1, %2, %3;" : "=l"(d) : "l"(a), "l"(b), "l"(c))
// out = {f, f}
#define BCAST2(out, f) \
    asm("mov.b64 %0, {%1, %1};" : "=l"(out) : "r"(__float_as_uint(f)))
#define UNPACK2(lo, hi, v) \
    asm("mov.b64 {%0, %1}, %2;" : "=r"(lo), "=r"(hi) : "l"(v))

union F4U2 { float4 f; u64t u[2]; };

__device__ __forceinline__ float lo_f(u64t v) {
    unsigned int l, h; UNPACK2(l, h, v); return __uint_as_float(l);
}
__device__ __forceinline__ float hi_f(u64t v) {
    unsigned int l, h; UNPACK2(l, h, v); return __uint_as_float(h);
}

// Scratch (device globals — allocation-free per harness rules)
__device__ float g_q [BATCH * DQK * NTOK];
__device__ float g_k [BATCH * DQK * NTOK];
__device__ float g_v [BATCH * CCH * NTOK];
__device__ float g_ao[BATCH * CCH * NTOK];

#define DST_Q   0
#define DST_K   1
#define DST_V   2
#define DST_OUT 3
#define SRC_X   0
#define SRC_AO  1

// ---------------------------------------------------------------------------
// Projection: out[b][o][n] = sum_c w[o][c] * x[b][c][n] + bias[o] (+ res)
// 64(o) x 64(n) block tile, 256 threads, 4x4 per-thread tile, f32x2 FMAs.
// ---------------------------------------------------------------------------
template <int OC, int DST, int SRC, bool RES>
__global__ __launch_bounds__(256) void proj_kernel(
    const float* __restrict__ xparam, const float* __restrict__ w,
    const float* __restrict__ bias, float* __restrict__ outparam)
{
    constexpr int IC = CCH;
    __shared__ float wt[16][64];   // wt[c][o]
    __shared__ float xs[16][64];   // xs[c][n]

    const int b = blockIdx.z;
    const float* xin = (SRC == SRC_X) ? xparam : (const float*)g_ao;
    float* outp = (DST == DST_Q) ? (float*)g_q
                : (DST == DST_K) ? (float*)g_k
                : (DST == DST_V) ? (float*)g_v : outparam;
    const float* xb = xin + (size_t)b * IC * NTOK;
    float* ob = outp + (size_t)b * OC * NTOK;

    const int ntile = blockIdx.x * 64;
    const int otile = blockIdx.y * 64;
    const int t  = threadIdx.x;
    const int og = t & 15, ng = t >> 4;
    const int o0 = og * 4, n0 = ng * 4;

    u64t acc2[4][2];
#pragma unroll
    for (int i = 0; i < 4; i++) { acc2[i][0] = 0ull; acc2[i][1] = 0ull; }

    for (int ct = 0; ct < IC; ct += 16) {
#pragma unroll
        for (int i = 0; i < 4; i++) {
            int idx = t + i * 256;
            int o = idx >> 4, cc = idx & 15;
            float val = 0.f;
            if (otile + o < OC) val = w[(size_t)(otile + o) * IC + ct + cc];
            wt[cc][o] = val;
        }
#pragma unroll
        for (int i = 0; i < 4; i++) {
            int idx = t + i * 256;
            int cc = idx >> 6, n = idx & 63;
            xs[cc][n] = xb[(size_t)(ct + cc) * NTOK + ntile + n];
        }
        __syncthreads();
#pragma unroll
        for (int cc = 0; cc < 16; cc++) {
            F4U2 w4, x4;
            w4.f = *(const float4*)&wt[cc][o0];
            x4.f = *(const float4*)&xs[cc][n0];
            float wv4[4] = {w4.f.x, w4.f.y, w4.f.z, w4.f.w};
            u64t wb[4];
#pragma unroll
            for (int oi = 0; oi < 4; oi++) BCAST2(wb[oi], wv4[oi]);
#pragma unroll
            for (int oi = 0; oi < 4; oi++) {
                FMA2(acc2[oi][0], wb[oi], x4.u[0], acc2[oi][0]);
                FMA2(acc2[oi][1], wb[oi], x4.u[1], acc2[oi][1]);
            }
        }
        __syncthreads();
    }

#pragma unroll
    for (int oi = 0; oi < 4; oi++) {
        int o = otile + o0 + oi;
        if (o < OC) {
            float bv = bias[o];
            size_t off = (size_t)o * NTOK + ntile + n0;
            float4 r;
            r.x = lo_f(acc2[oi][0]) + bv; r.y = hi_f(acc2[oi][0]) + bv;
            r.z = lo_f(acc2[oi][1]) + bv; r.w = hi_f(acc2[oi][1]) + bv;
            if (RES) {
                const float* rb = xparam + (size_t)b * OC * NTOK;
                float4 rr = *(const float4*)&rb[off];
                r.x += rr.x; r.y += rr.y; r.z += rr.z; r.w += rr.w;
            }
            *(float4*)&ob[off] = r;
        }
    }
}

// ---------------------------------------------------------------------------
// QK^T micro-tile: s[4][4] for one (m0, j0) group from SMEM q/k tiles.
// ---------------------------------------------------------------------------
__device__ __forceinline__ void qk_tile(const float* qs, const float* ks,
                                        int m0, int j0, float s[4][4])
{
    u64t s2[4][2];
#pragma unroll
    for (int i = 0; i < 4; i++) { s2[i][0] = 0ull; s2[i][1] = 0ull; }
#pragma unroll
    for (int d = 0; d < DQK; d++) {
        F4U2 q4, k4;
        q4.f = *(const float4*)(qs + d * BM + m0);
        k4.f = *(const float4*)(ks + d * BN + j0);
        float qv[4] = {q4.f.x, q4.f.y, q4.f.z, q4.f.w};
        u64t qb[4];
#pragma unroll
        for (int mi = 0; mi < 4; mi++) BCAST2(qb[mi], qv[mi]);
#pragma unroll
        for (int mi = 0; mi < 4; mi++) {
            FMA2(s2[mi][0], qb[mi], k4.u[0], s2[mi][0]);
            FMA2(s2[mi][1], qb[mi], k4.u[1], s2[mi][1]);
        }
    }
#pragma unroll
    for (int mi = 0; mi < 4; mi++) {
        s[mi][0] = lo_f(s2[mi][0]); s[mi][1] = hi_f(s2[mi][0]);
        s[mi][2] = lo_f(s2[mi][1]); s[mi][3] = hi_f(s2[mi][1]);
    }
}

// ---------------------------------------------------------------------------
// Attention: one block per (64-query tile, batch). 256 threads, two passes.
// ---------------------------------------------------------------------------
__global__ __launch_bounds__(256) void attn_kernel()
{
    extern __shared__ float sm[];
    float* qs     = sm;                    // [DQK][BM]
    float* ks     = qs + DQK * BM;         // [DQK][BN]
    float* pt     = ks + DQK * BN;         // [BN][PT_S]
    float* vt     = pt + BN * PT_S;        // [BN][VT_S]
    float* redm   = vt + BN * VT_S;        // [16][BM]
    float* reds   = redm + 16 * BM;        // [16][BM]
    float* rowmax = reds + 16 * BM;        // [BM]
    float* rowinv = rowmax + BM;           // [BM]

    const int b  = blockIdx.y;
    const int q0 = blockIdx.x * BM;
    const int t  = threadIdx.x;

    const float* qb = g_q + (size_t)b * DQK * NTOK;
    const float* kb = g_k + (size_t)b * DQK * NTOK;
    const float* vb = g_v + (size_t)b * CCH * NTOK;
    float*       ob = g_ao + (size_t)b * CCH * NTOK;

#pragma unroll
    for (int i = 0; i < (DQK * BM) / 256; i++) {
        int idx = t + i * 256;
        int d = idx >> 6, m = idx & 63;
        qs[d * BM + m] = qb[(size_t)d * NTOK + q0 + m];
    }

    const int mg = t & 15, jg = t >> 4;
    const int m0 = mg * 4, j0 = jg * 4;

    float tmax[4], tsum[4];
#pragma unroll
    for (int i = 0; i < 4; i++) { tmax[i] = -1e30f; tsum[i] = 0.f; }

    // ---------------- Pass 1: row statistics ----------------
    for (int nc = 0; nc < NTOK; nc += BN) {
#pragma unroll
        for (int i = 0; i < (DQK * BN) / 256; i++) {
            int idx = t + i * 256;
            int d = idx >> 6, j = idx & 63;
            ks[d * BN + j] = kb[(size_t)d * NTOK + nc + j];
        }
        __syncthreads();

        float s[4][4];
        qk_tile(qs, ks, m0, j0, s);

#pragma unroll
        for (int mi = 0; mi < 4; mi++) {
            float cm = fmaxf(fmaxf(s[mi][0], s[mi][1]), fmaxf(s[mi][2], s[mi][3]));
            float nm = fmaxf(tmax[mi], cm);
            float add = __expf(s[mi][0] - nm) + __expf(s[mi][1] - nm)
                      + __expf(s[mi][2] - nm) + __expf(s[mi][3] - nm);
            tsum[mi] = tsum[mi] * __expf(tmax[mi] - nm) + add;
            tmax[mi] = nm;
        }
        __syncthreads();
    }

#pragma unroll
    for (int mi = 0; mi < 4; mi++) {
        redm[jg * BM + m0 + mi] = tmax[mi];
        reds[jg * BM + m0 + mi] = tsum[mi];
    }
    __syncthreads();
    if (t < BM) {
        float M = -1e30f, S = 0.f;
#pragma unroll
        for (int g2 = 0; g2 < 16; g2++) {
            float m2 = redm[g2 * BM + t];
            float s2 = reds[g2 * BM + t];
            float nm = fmaxf(M, m2);
            S = S * __expf(M - nm) + s2 * __expf(m2 - nm);
            M = nm;
        }
        rowmax[t] = M;
        rowinv[t] = 1.f / S;
    }
    __syncthreads();

    // ---------------- Pass 2: P.V accumulation ----------------
    const int a = t & 7, g = t >> 3;
    const int mp0 = a * 8, c0 = g * 8;

    float rm[4];
#pragma unroll
    for (int mi = 0; mi < 4; mi++) rm[mi] = rowmax[m0 + mi];

    u64t acc2[8][4];   // pairs along channel dim: acc2[mi][cp] = {c0+2cp, c0+2cp+1}
#pragma unroll
    for (int mi = 0; mi < 8; mi++)
#pragma unroll
        for (int cp = 0; cp < 4; cp++) acc2[mi][cp] = 0ull;

    for (int nc = 0; nc < NTOK; nc += BN) {
#pragma unroll
        for (int i = 0; i < (DQK * BN) / 256; i++) {
            int idx = t + i * 256;
            int d = idx >> 6, j = idx & 63;
            ks[d * BN + j] = kb[(size_t)d * NTOK + nc + j];
        }
#pragma unroll
        for (int i = 0; i < (CCH * BN) / 256; i++) {
            int idx = t + i * 256;
            int c = idx >> 6, j = idx & 63;
            vt[j * VT_S + c] = vb[(size_t)c * NTOK + nc + j];
        }
        __syncthreads();

        float s[4][4];
        qk_tile(qs, ks, m0, j0, s);

#pragma unroll
        for (int ji = 0; ji < 4; ji++) {
            float4 p4;
            p4.x = __expf(s[0][ji] - rm[0]);
            p4.y = __expf(s[1][ji] - rm[1]);
            p4.z = __expf(s[2][ji] - rm[2]);
            p4.w = __expf(s[3][ji] - rm[3]);
            *(float4*)(pt + (j0 + ji) * PT_S + m0) = p4;
        }
        __syncthreads();

#pragma unroll 4
        for (int j = 0; j < BN; j++) {
            float4 pA = *(const float4*)(pt + j * PT_S + mp0);
            float4 pB = *(const float4*)(pt + j * PT_S + mp0 + 4);
            F4U2 vA, vB;
            vA.f = *(const float4*)(vt + j * VT_S + c0);
            vB.f = *(const float4*)(vt + j * VT_S + c0 + 4);
            float pv[8] = {pA.x, pA.y, pA.z, pA.w, pB.x, pB.y, pB.z, pB.w};
            u64t pb2[8];
#pragma unroll
            for (int mi = 0; mi < 8; mi++) BCAST2(pb2[mi], pv[mi]);
#pragma unroll
            for (int mi = 0; mi < 8; mi++) {
                FMA2(acc2[mi][0], pb2[mi], vA.u[0], acc2[mi][0]);
                FMA2(acc2[mi][1], pb2[mi], vA.u[1], acc2[mi][1]);
                FMA2(acc2[mi][2], pb2[mi], vB.u[0], acc2[mi][2]);
                FMA2(acc2[mi][3], pb2[mi], vB.u[1], acc2[mi][3]);
            }
        }
        __syncthreads();
    }

    // Epilogue: normalize and write O[b][c][m]
    float inv[8];
#pragma unroll
    for (int mi = 0; mi < 8; mi++) inv[mi] = rowinv[mp0 + mi];
#pragma unroll
    for (int cp = 0; cp < 4; cp++) {
        int cA = c0 + 2 * cp, cB = cA + 1;
        float4 oA, oB;
        oA.x = lo_f(acc2[0][cp]) * inv[0]; oA.y = lo_f(acc2[1][cp]) * inv[1];
        oA.z = lo_f(acc2[2][cp]) * inv[2]; oA.w = lo_f(acc2[3][cp]) * inv[3];
        float4 oA2;
        oA2.x = lo_f(acc2[4][cp]) * inv[4]; oA2.y = lo_f(acc2[5][cp]) * inv[5];
        oA2.z = lo_f(acc2[6][cp]) * inv[6]; oA2.w = lo_f(acc2[7][cp]) * inv[7];
        oB.x = hi_f(acc2[0][cp]) * inv[0]; oB.y = hi_f(acc2[1][cp]) * inv[1];
        oB.z = hi_f(acc2[2][cp]) * inv[2]; oB.w = hi_f(acc2[3][cp]) * inv[3];
        float4 oB2;
        oB2.x = hi_f(acc2[4][cp]) * inv[4]; oB2.y = hi_f(acc2[5][cp]) * inv[5];
        oB2.z = hi_f(acc2[6][cp]) * inv[6]; oB2.w = hi_f(acc2[7][cp]) * inv[7];
        size_t offA = (size_t)cA * NTOK + q0 + mp0;
        size_t offB = (size_t)cB * NTOK + q0 + mp0;
        *(float4*)(ob + offA)     = oA;
        *(float4*)(ob + offA + 4) = oA2;
        *(float4*)(ob + offB)     = oB;
        *(float4*)(ob + offB + 4) = oB2;
    }
}

// ---------------------------------------------------------------------------

static const int ATTN_SMEM_BYTES =
    (DQK * BM + DQK * BN + BN * PT_S + BN * VT_S + 16 * BM * 2 + BM * 2) * (int)sizeof(float);

extern "C" void kernel_launch(void* const* d_in, const int* in_sizes, int n_in,
                              void* d_out, int out_size)
{
    const float* x  = (const float*)d_in[0];
    const float* wq = (const float*)d_in[1];
    const float* bq = (const float*)d_in[2];
    const float* wk = (const float*)d_in[3];
    const float* bk = (const float*)d_in[4];
    const float* wv = (const float*)d_in[5];
    const float* bv = (const float*)d_in[6];
    const float* wo = (const float*)d_in[7];
    const float* bo = (const float*)d_in[8];
    float* out = (float*)d_out;

    cudaFuncSetAttribute(attn_kernel, cudaFuncAttributeMaxDynamicSharedMemorySize,
                         ATTN_SMEM_BYTES);

    dim3 blk(256);
    proj_kernel<DQK, DST_Q, SRC_X, false><<<dim3(NTOK / 64, 1, BATCH), blk>>>(x, wq, bq, nullptr);
    proj_kernel<DQK, DST_K, SRC_X, false><<<dim3(NTOK / 64, 1, BATCH), blk>>>(x, wk, bk, nullptr);
    proj_kernel<CCH, DST_V, SRC_X, false><<<dim3(NTOK / 64, CCH / 64, BATCH), blk>>>(x, wv, bv, nullptr);
    attn_kernel<<<dim3(NTOK / BM, BATCH), blk, ATTN_SMEM_BYTES>>>();
    proj_kernel<CCH, DST_OUT, SRC_AO, true><<<dim3(NTOK / 64, CCH / 64, BATCH), blk>>>(x, wo, bo, out);
}

// round 5
// speedup vs baseline: 2.4901x; 2.4901x over previous
#include <cuda_runtime.h>
#include <cuda_bf16.h>
#include <cstdint>
#include <cstddef>

// ---------------------------------------------------------------------------
// ComplexSpatialAttentionModule, sm_100 (non-'a' PTX target): tensor cores via
// mma.sync.m16n8k16 bf16 + ldmatrix. B=4, C=256, N=4096, DQK=32.
// Projections (f32x2 SIMT) emit bf16 hi/lo splits; flash attention uses
// 3-term bf16 products (err ~2^-16) with a two-pass fixed-max softmax.
// ---------------------------------------------------------------------------

#define BATCH 4
#define CCH   256
#define DQK   32
#define NTOK  4096

typedef unsigned long long u64t;

// ----- packed f32x2 helpers (projection kernels) -----
#define FMA2(d, a, b, c) \
    asm("fma.rn.f32x2 %0, %1, %2, %3;" : "=l"(d) : "l"(a), "l"(b), "l"(c))
#define BCAST2(out, f) \
    asm("mov.b64 %0, {%1, %1};" : "=l"(out) : "r"(__float_as_uint(f)))
#define UNPACK2(lo, hi, v) \
    asm("mov.b64 {%0, %1}, %2;" : "=r"(lo), "=r"(hi) : "l"(v))
union F4U2 { float4 f; u64t u[2]; };
__device__ __forceinline__ float lo_f(u64t v) {
    unsigned int l, h; UNPACK2(l, h, v); return __uint_as_float(l);
}
__device__ __forceinline__ float hi_f(u64t v) {
    unsigned int l, h; UNPACK2(l, h, v); return __uint_as_float(h);
}

// ----- bf16 split/pack helpers -----
__device__ __forceinline__ uint32_t pk2(float lo, float hi) {
    uint32_t u;
    asm("cvt.rn.bf16x2.f32 %0, %1, %2;" : "=r"(u) : "f"(hi), "f"(lo));
    return u;
}
__device__ __forceinline__ void bsp(float x, float& h, float& l) {
    __nv_bfloat16 hb = __float2bfloat16(x);
    h = __bfloat162float(hb);
    l = x - h;
}

// ----- scratch (device globals) -----
// q/k token-major: 16 bf16x2 words per token (32 dims)
__device__ __align__(16) uint32_t g_qh[BATCH * NTOK * 16];
__device__ __align__(16) uint32_t g_ql[BATCH * NTOK * 16];
__device__ __align__(16) uint32_t g_kh[BATCH * NTOK * 16];
__device__ __align__(16) uint32_t g_kl[BATCH * NTOK * 16];
// v channel-major: 2048 words per channel row (4096 tokens)
__device__ __align__(16) uint32_t g_vh[BATCH * CCH * (NTOK / 2)];
__device__ __align__(16) uint32_t g_vl[BATCH * CCH * (NTOK / 2)];
__device__ float g_ao[BATCH * CCH * NTOK];

#define DST_Q   0
#define DST_K   1
#define DST_V   2
#define DST_OUT 3

// ---------------------------------------------------------------------------
// Projection: out[o][n] = sum_c w[o][c] x[c][n] + b[o]. 64x64 tile, f32x2.
// ---------------------------------------------------------------------------
template <int OC, int DST, bool RES>
__global__ __launch_bounds__(256) void proj_kernel(
    const float* __restrict__ xparam, const float* __restrict__ w,
    const float* __restrict__ bias, float* __restrict__ outparam)
{
    constexpr int IC = CCH;
    __shared__ float wt[16][64];
    __shared__ float xs[16][64];

    const int b = blockIdx.z;
    const float* xin = (DST == DST_OUT) ? (const float*)g_ao : xparam;
    const float* xb = xin + (size_t)b * IC * NTOK;

    const int ntile = blockIdx.x * 64;
    const int otile = blockIdx.y * 64;
    const int t  = threadIdx.x;
    const int og = t & 15, ng = t >> 4;
    const int o0 = og * 4, n0 = ng * 4;

    u64t acc2[4][2];
#pragma unroll
    for (int i = 0; i < 4; i++) { acc2[i][0] = 0ull; acc2[i][1] = 0ull; }

    for (int ct = 0; ct < IC; ct += 16) {
#pragma unroll
        for (int i = 0; i < 4; i++) {
            int idx = t + i * 256;
            int o = idx >> 4, cc = idx & 15;
            float val = 0.f;
            if (otile + o < OC) val = w[(size_t)(otile + o) * IC + ct + cc];
            wt[cc][o] = val;
        }
#pragma unroll
        for (int i = 0; i < 4; i++) {
            int idx = t + i * 256;
            int cc = idx >> 6, n = idx & 63;
            xs[cc][n] = xb[(size_t)(ct + cc) * NTOK + ntile + n];
        }
        __syncthreads();
#pragma unroll
        for (int cc = 0; cc < 16; cc++) {
            F4U2 w4, x4;
            w4.f = *(const float4*)&wt[cc][o0];
            x4.f = *(const float4*)&xs[cc][n0];
            float wv4[4] = {w4.f.x, w4.f.y, w4.f.z, w4.f.w};
            u64t wb[4];
#pragma unroll
            for (int oi = 0; oi < 4; oi++) BCAST2(wb[oi], wv4[oi]);
#pragma unroll
            for (int oi = 0; oi < 4; oi++) {
                FMA2(acc2[oi][0], wb[oi], x4.u[0], acc2[oi][0]);
                FMA2(acc2[oi][1], wb[oi], x4.u[1], acc2[oi][1]);
            }
        }
        __syncthreads();
    }

    float vals[4][4];
#pragma unroll
    for (int oi = 0; oi < 4; oi++) {
        vals[oi][0] = lo_f(acc2[oi][0]); vals[oi][1] = hi_f(acc2[oi][0]);
        vals[oi][2] = lo_f(acc2[oi][1]); vals[oi][3] = hi_f(acc2[oi][1]);
    }

    if (DST == DST_Q || DST == DST_K) {
        if (o0 < DQK) {
            uint32_t* gh = ((DST == DST_Q) ? g_qh : g_kh) + (size_t)b * NTOK * 16;
            uint32_t* gl = ((DST == DST_Q) ? g_ql : g_kl) + (size_t)b * NTOK * 16;
            float bv[4] = {bias[o0], bias[o0 + 1], bias[o0 + 2], bias[o0 + 3]};
#pragma unroll
            for (int ni = 0; ni < 4; ni++) {
                float h[4], l[4];
#pragma unroll
                for (int oi = 0; oi < 4; oi++) bsp(vals[oi][ni] + bv[oi], h[oi], l[oi]);
                size_t widx = (size_t)(ntile + n0 + ni) * 16 + (o0 >> 1);
                *(uint2*)(gh + widx) = make_uint2(pk2(h[0], h[1]), pk2(h[2], h[3]));
                *(uint2*)(gl + widx) = make_uint2(pk2(l[0], l[1]), pk2(l[2], l[3]));
            }
        }
    } else if (DST == DST_V) {
#pragma unroll
        for (int oi = 0; oi < 4; oi++) {
            int o = otile + o0 + oi;
            float bv = bias[o];
            float h[4], l[4];
#pragma unroll
            for (int ni = 0; ni < 4; ni++) bsp(vals[oi][ni] + bv, h[ni], l[ni]);
            size_t widx = ((size_t)b * CCH + o) * (NTOK / 2) + ((ntile + n0) >> 1);
            *(uint2*)(g_vh + widx) = make_uint2(pk2(h[0], h[1]), pk2(h[2], h[3]));
            *(uint2*)(g_vl + widx) = make_uint2(pk2(l[0], l[1]), pk2(l[2], l[3]));
        }
    } else {
        float* ob = outparam + (size_t)b * OC * NTOK;
        const float* rb = xparam + (size_t)b * OC * NTOK;
#pragma unroll
        for (int oi = 0; oi < 4; oi++) {
            int o = otile + o0 + oi;
            float bv = bias[o];
            size_t off = (size_t)o * NTOK + ntile + n0;
            float4 r;
            r.x = vals[oi][0] + bv; r.y = vals[oi][1] + bv;
            r.z = vals[oi][2] + bv; r.w = vals[oi][3] + bv;
            if (RES) {
                float4 rr = *(const float4*)&rb[off];
                r.x += rr.x; r.y += rr.y; r.z += rr.z; r.w += rr.w;
            }
            *(float4*)&ob[off] = r;
        }
    }
}

// ---------------------------------------------------------------------------
// mma.sync / ldmatrix helpers
// ---------------------------------------------------------------------------
__device__ __forceinline__ uint32_t smem_u32(const void* p) {
    uint32_t a;
    asm("{ .reg .u64 t; cvta.to.shared.u64 t, %1; cvt.u32.u64 %0, t; }"
        : "=r"(a) : "l"(p));
    return a;
}
__device__ __forceinline__ void ldsm4(uint32_t addr, uint32_t& r0, uint32_t& r1,
                                      uint32_t& r2, uint32_t& r3) {
    asm volatile("ldmatrix.sync.aligned.m8n8.x4.shared.b16 {%0,%1,%2,%3}, [%4];"
                 : "=r"(r0), "=r"(r1), "=r"(r2), "=r"(r3) : "r"(addr));
}
__device__ __forceinline__ void mmabf(float* d, const uint32_t* a,
                                      uint32_t b0, uint32_t b1) {
    asm volatile(
        "mma.sync.aligned.m16n8k16.row.col.f32.bf16.bf16.f32 "
        "{%0,%1,%2,%3}, {%4,%5,%6,%7}, {%8,%9}, {%0,%1,%2,%3};"
        : "+f"(d[0]), "+f"(d[1]), "+f"(d[2]), "+f"(d[3])
        : "r"(a[0]), "r"(a[1]), "r"(a[2]), "r"(a[3]), "r"(b0), "r"(b1));
}

// ---------------------------------------------------------------------------
// Attention: 128 q-rows/CTA, 8 warps x 16 rows, JT=64 keys/tile, two passes.
// SMEM (bytes): QH 0, QL 10240 (128x40 bf16, 80B rows); KH 20480, KL 25600
// (64x40); VH 30720, VL 67584 (256x72 bf16, 144B rows). Total 104448.
// ---------------------------------------------------------------------------
#define SM_QH 0
#define SM_QL 10240
#define SM_KH 20480
#define SM_KL 25600
#define SM_VH 30720
#define SM_VL 67584
#define ATTN_SMEM 104448

__global__ __launch_bounds__(256) void attn_mma_kernel()
{
    extern __shared__ __align__(16) char smem[];
    const int t = threadIdx.x, lane = t & 31, w = t >> 5;
    const int b = blockIdx.y, q0 = blockIdx.x * 128;
    const uint32_t sb = smem_u32(smem);

    // ---- Q tile -> SMEM (hi/lo) ----
    {
        int row = t >> 1;
        size_t gidx = ((size_t)b * NTOK + q0 + row) * 4 + (t & 1) * 2;
        const uint4* sh = (const uint4*)g_qh + gidx;
        const uint4* sl = (const uint4*)g_ql + gidx;
        uint4* dh = (uint4*)(smem + SM_QH + row * 80 + (t & 1) * 32);
        uint4* dl = (uint4*)(smem + SM_QL + row * 80 + (t & 1) * 32);
        dh[0] = sh[0]; dh[1] = sh[1];
        dl[0] = sl[0]; dl[1] = sl[1];
    }
    __syncthreads();

    // ---- preload Q A-fragments ----
    const int a_row  = (lane & 7) + (lane & 8);
    const int a_kofs = (lane & 16) ? 8 : 0;
    const int b_row  = (lane & 7) + ((lane & 16) ? 8 : 0);
    const int b_kofs = (lane & 8);

    uint32_t qa_h[2][4], qa_l[2][4];
#pragma unroll
    for (int kc = 0; kc < 2; kc++) {
        uint32_t byteoff = (uint32_t)(w * 16 + a_row) * 80 + (kc * 16 + a_kofs) * 2;
        ldsm4(sb + SM_QH + byteoff, qa_h[kc][0], qa_h[kc][1], qa_h[kc][2], qa_h[kc][3]);
        ldsm4(sb + SM_QL + byteoff, qa_l[kc][0], qa_l[kc][1], qa_l[kc][2], qa_l[kc][3]);
    }

    float M0 = -1e30f, M1 = -1e30f;

    // ================= Pass 1: row max (hi-only) =================
    for (int nc = 0; nc < NTOK; nc += 64) {
        __syncthreads();
        {
            int row = t >> 2, q = t & 3;
            *(uint4*)(smem + SM_KH + row * 80 + q * 16) =
                ((const uint4*)g_kh)[((size_t)b * NTOK + nc + row) * 4 + q];
        }
        __syncthreads();

        float sfr[8][4];
#pragma unroll
        for (int i = 0; i < 8; i++)
#pragma unroll
            for (int j = 0; j < 4; j++) sfr[i][j] = 0.f;

#pragma unroll
        for (int nfp = 0; nfp < 4; nfp++)
#pragma unroll
            for (int kc = 0; kc < 2; kc++) {
                uint32_t ad = sb + SM_KH + (uint32_t)(nfp * 16 + b_row) * 80
                            + (kc * 16 + b_kofs) * 2;
                uint32_t h0, h1, h2, h3;
                ldsm4(ad, h0, h1, h2, h3);
                mmabf(sfr[2 * nfp],     qa_h[kc], h0, h1);
                mmabf(sfr[2 * nfp + 1], qa_h[kc], h2, h3);
            }
#pragma unroll
        for (int nf = 0; nf < 8; nf++) {
            M0 = fmaxf(M0, fmaxf(sfr[nf][0], sfr[nf][1]));
            M1 = fmaxf(M1, fmaxf(sfr[nf][2], sfr[nf][3]));
        }
    }
    M0 = fmaxf(M0, __shfl_xor_sync(0xffffffffu, M0, 1));
    M0 = fmaxf(M0, __shfl_xor_sync(0xffffffffu, M0, 2));
    M1 = fmaxf(M1, __shfl_xor_sync(0xffffffffu, M1, 1));
    M1 = fmaxf(M1, __shfl_xor_sync(0xffffffffu, M1, 2));

    // ================= Pass 2 =================
    float o[32][4];
#pragma unroll
    for (int i = 0; i < 32; i++)
#pragma unroll
        for (int j = 0; j < 4; j++) o[i][j] = 0.f;
    float sum0 = 0.f, sum1 = 0.f;

    for (int nc = 0; nc < NTOK; nc += 64) {
        __syncthreads();
        {
            int row = t >> 2, q = t & 3;
            size_t gk = ((size_t)b * NTOK + nc + row) * 4 + q;
            *(uint4*)(smem + SM_KH + row * 80 + q * 16) = ((const uint4*)g_kh)[gk];
            *(uint4*)(smem + SM_KL + row * 80 + q * 16) = ((const uint4*)g_kl)[gk];
        }
#pragma unroll
        for (int i = 0; i < 8; i++) {
            int row = (t >> 3) + i * 32, q = t & 7;
            size_t gv = ((size_t)b * CCH + row) * 512 + (nc >> 3) + q;
            uint32_t so = (uint32_t)row * 144 + q * 16;
            *(uint4*)(smem + SM_VH + so) = ((const uint4*)g_vh)[gv];
            *(uint4*)(smem + SM_VL + so) = ((const uint4*)g_vl)[gv];
        }
        __syncthreads();

        // ---- S = Q.K^T (3-term) ----
        float sfr[8][4];
#pragma unroll
        for (int i = 0; i < 8; i++)
#pragma unroll
            for (int j = 0; j < 4; j++) sfr[i][j] = 0.f;

#pragma unroll
        for (int nfp = 0; nfp < 4; nfp++)
#pragma unroll
            for (int kc = 0; kc < 2; kc++) {
                uint32_t boff = (uint32_t)(nfp * 16 + b_row) * 80 + (kc * 16 + b_kofs) * 2;
                uint32_t h0, h1, h2, h3, l0, l1, l2, l3;
                ldsm4(sb + SM_KH + boff, h0, h1, h2, h3);
                ldsm4(sb + SM_KL + boff, l0, l1, l2, l3);
                mmabf(sfr[2 * nfp],     qa_h[kc], h0, h1);
                mmabf(sfr[2 * nfp + 1], qa_h[kc], h2, h3);
                mmabf(sfr[2 * nfp],     qa_h[kc], l0, l1);
                mmabf(sfr[2 * nfp + 1], qa_h[kc], l2, l3);
                mmabf(sfr[2 * nfp],     qa_l[kc], h0, h1);
                mmabf(sfr[2 * nfp + 1], qa_l[kc], h2, h3);
            }

        // ---- P = exp(S - M), pack as bf16 hi/lo A-fragments ----
        uint32_t pah[4][4], pal[4][4];
#pragma unroll
        for (int kc = 0; kc < 4; kc++) {
            int fa = 2 * kc, fb = 2 * kc + 1;
            float p[8];
            p[0] = __expf(sfr[fa][0] - M0); p[1] = __expf(sfr[fa][1] - M0);
            p[2] = __expf(sfr[fa][2] - M1); p[3] = __expf(sfr[fa][3] - M1);
            p[4] = __expf(sfr[fb][0] - M0); p[5] = __expf(sfr[fb][1] - M0);
            p[6] = __expf(sfr[fb][2] - M1); p[7] = __expf(sfr[fb][3] - M1);
            sum0 += p[0] + p[1] + p[4] + p[5];
            sum1 += p[2] + p[3] + p[6] + p[7];
            float h[8], l[8];
#pragma unroll
            for (int i = 0; i < 8; i++) bsp(p[i], h[i], l[i]);
            pah[kc][0] = pk2(h[0], h[1]); pah[kc][1] = pk2(h[2], h[3]);
            pah[kc][2] = pk2(h[4], h[5]); pah[kc][3] = pk2(h[6], h[7]);
            pal[kc][0] = pk2(l[0], l[1]); pal[kc][1] = pk2(l[2], l[3]);
            pal[kc][2] = pk2(l[4], l[5]); pal[kc][3] = pk2(l[6], l[7]);
        }

        // ---- O += P.V^T (3-term) ----
#pragma unroll
        for (int nfp = 0; nfp < 16; nfp++)
#pragma unroll
            for (int kc = 0; kc < 4; kc++) {
                uint32_t boff = (uint32_t)(nfp * 16 + b_row) * 144 + (kc * 16 + b_kofs) * 2;
                uint32_t h0, h1, h2, h3, l0, l1, l2, l3;
                ldsm4(sb + SM_VH + boff, h0, h1, h2, h3);
                ldsm4(sb + SM_VL + boff, l0, l1, l2, l3);
                mmabf(o[2 * nfp],     pah[kc], h0, h1);
                mmabf(o[2 * nfp + 1], pah[kc], h2, h3);
                mmabf(o[2 * nfp],     pah[kc], l0, l1);
                mmabf(o[2 * nfp + 1], pah[kc], l2, l3);
                mmabf(o[2 * nfp],     pal[kc], h0, h1);
                mmabf(o[2 * nfp + 1], pal[kc], h2, h3);
            }
    }

    sum0 += __shfl_xor_sync(0xffffffffu, sum0, 1);
    sum0 += __shfl_xor_sync(0xffffffffu, sum0, 2);
    sum1 += __shfl_xor_sync(0xffffffffu, sum1, 1);
    sum1 += __shfl_xor_sync(0xffffffffu, sum1, 2);
    const float inv0 = 1.f / sum0, inv1 = 1.f / sum1;

    // ---- epilogue: O/sum -> g_ao[b][c][n] ----
    {
        float* aob = g_ao + (size_t)b * CCH * NTOK;
        const int r = lane >> 2, qd = lane & 3;
        const int n_g = q0 + w * 16 + r;
#pragma unroll
        for (int nf = 0; nf < 32; nf++) {
            int c0 = nf * 8 + qd * 2;
            aob[(size_t)c0 * NTOK + n_g]           = o[nf][0] * inv0;
            aob[(size_t)(c0 + 1) * NTOK + n_g]     = o[nf][1] * inv0;
            aob[(size_t)c0 * NTOK + n_g + 8]       = o[nf][2] * inv1;
            aob[(size_t)(c0 + 1) * NTOK + n_g + 8] = o[nf][3] * inv1;
        }
    }
}

// ---------------------------------------------------------------------------

extern "C" void kernel_launch(void* const* d_in, const int* in_sizes, int n_in,
                              void* d_out, int out_size)
{
    const float* x  = (const float*)d_in[0];
    const float* wq = (const float*)d_in[1];
    const float* bq = (const float*)d_in[2];
    const float* wk = (const float*)d_in[3];
    const float* bk = (const float*)d_in[4];
    const float* wv = (const float*)d_in[5];
    const float* bv = (const float*)d_in[6];
    const float* wo = (const float*)d_in[7];
    const float* bo = (const float*)d_in[8];
    float* out = (float*)d_out;

    cudaFuncSetAttribute(attn_mma_kernel, cudaFuncAttributeMaxDynamicSharedMemorySize,
                         ATTN_SMEM);

    dim3 blk(256);
    proj_kernel<DQK, DST_Q,  false><<<dim3(NTOK / 64, 1, BATCH), blk>>>(x, wq, bq, nullptr);
    proj_kernel<DQK, DST_K,  false><<<dim3(NTOK / 64, 1, BATCH), blk>>>(x, wk, bk, nullptr);
    proj_kernel<CCH, DST_V,  false><<<dim3(NTOK / 64, CCH / 64, BATCH), blk>>>(x, wv, bv, nullptr);
    attn_mma_kernel<<<dim3(NTOK / 128, BATCH), blk, ATTN_SMEM>>>();
    proj_kernel<CCH, DST_OUT, true><<<dim3(NTOK / 64, CCH / 64, BATCH), blk>>>(x, wo, bo, out);
}

// round 6
// speedup vs baseline: 2.6082x; 1.0474x over previous
#include <cuda_runtime.h>
#include <cuda_bf16.h>
#include <cstdint>
#include <cstddef>

// ---------------------------------------------------------------------------
// ComplexSpatialAttentionModule, sm_100 PTX target: mma.sync m16n8k16 bf16
// flash attention, single-pass online softmax, cp.async double-buffered K/V.
// Projections (f32x2 SIMT) emit bf16 hi/lo splits. 3-term bf16 products.
// ---------------------------------------------------------------------------

#define BATCH 4
#define CCH   256
#define DQK   32
#define NTOK  4096

typedef unsigned long long u64t;

// ----- packed f32x2 helpers (projection kernels) -----
#define FMA2(d, a, b, c) \
    asm("fma.rn.f32x2 %0, %1, %2, %3;" : "=l"(d) : "l"(a), "l"(b), "l"(c))
#define BCAST2(out, f) \
    asm("mov.b64 %0, {%1, %1};" : "=l"(out) : "r"(__float_as_uint(f)))
#define UNPACK2(lo, hi, v) \
    asm("mov.b64 {%0, %1}, %2;" : "=r"(lo), "=r"(hi) : "l"(v))
union F4U2 { float4 f; u64t u[2]; };
__device__ __forceinline__ float lo_f(u64t v) {
    unsigned int l, h; UNPACK2(l, h, v); return __uint_as_float(l);
}
__device__ __forceinline__ float hi_f(u64t v) {
    unsigned int l, h; UNPACK2(l, h, v); return __uint_as_float(h);
}

// ----- bf16 split/pack helpers -----
__device__ __forceinline__ uint32_t pk2(float lo, float hi) {
    uint32_t u;
    asm("cvt.rn.bf16x2.f32 %0, %1, %2;" : "=r"(u) : "f"(hi), "f"(lo));
    return u;
}
__device__ __forceinline__ void bsp(float x, float& h, float& l) {
    __nv_bfloat16 hb = __float2bfloat16(x);
    h = __bfloat162float(hb);
    l = x - h;
}

// ----- scratch (device globals) -----
__device__ __align__(16) uint32_t g_qh[BATCH * NTOK * 16];
__device__ __align__(16) uint32_t g_ql[BATCH * NTOK * 16];
__device__ __align__(16) uint32_t g_kh[BATCH * NTOK * 16];
__device__ __align__(16) uint32_t g_kl[BATCH * NTOK * 16];
__device__ __align__(16) uint32_t g_vh[BATCH * CCH * (NTOK / 2)];
__device__ __align__(16) uint32_t g_vl[BATCH * CCH * (NTOK / 2)];
__device__ float g_ao[BATCH * CCH * NTOK];

#define DST_Q   0
#define DST_K   1
#define DST_V   2
#define DST_OUT 3

// ---------------------------------------------------------------------------
// Projection: out[o][n] = sum_c w[o][c] x[c][n] + b[o]. 64x64 tile, f32x2.
// ---------------------------------------------------------------------------
template <int OC, int DST, bool RES>
__global__ __launch_bounds__(256) void proj_kernel(
    const float* __restrict__ xparam, const float* __restrict__ w,
    const float* __restrict__ bias, float* __restrict__ outparam)
{
    constexpr int IC = CCH;
    __shared__ float wt[16][64];
    __shared__ float xs[16][64];

    const int b = blockIdx.z;
    const float* xin = (DST == DST_OUT) ? (const float*)g_ao : xparam;
    const float* xb = xin + (size_t)b * IC * NTOK;

    const int ntile = blockIdx.x * 64;
    const int otile = blockIdx.y * 64;
    const int t  = threadIdx.x;
    const int og = t & 15, ng = t >> 4;
    const int o0 = og * 4, n0 = ng * 4;

    u64t acc2[4][2];
#pragma unroll
    for (int i = 0; i < 4; i++) { acc2[i][0] = 0ull; acc2[i][1] = 0ull; }

    for (int ct = 0; ct < IC; ct += 16) {
#pragma unroll
        for (int i = 0; i < 4; i++) {
            int idx = t + i * 256;
            int o = idx >> 4, cc = idx & 15;
            float val = 0.f;
            if (otile + o < OC) val = w[(size_t)(otile + o) * IC + ct + cc];
            wt[cc][o] = val;
        }
#pragma unroll
        for (int i = 0; i < 4; i++) {
            int idx = t + i * 256;
            int cc = idx >> 6, n = idx & 63;
            xs[cc][n] = xb[(size_t)(ct + cc) * NTOK + ntile + n];
        }
        __syncthreads();
#pragma unroll
        for (int cc = 0; cc < 16; cc++) {
            F4U2 w4, x4;
            w4.f = *(const float4*)&wt[cc][o0];
            x4.f = *(const float4*)&xs[cc][n0];
            float wv4[4] = {w4.f.x, w4.f.y, w4.f.z, w4.f.w};
            u64t wb[4];
#pragma unroll
            for (int oi = 0; oi < 4; oi++) BCAST2(wb[oi], wv4[oi]);
#pragma unroll
            for (int oi = 0; oi < 4; oi++) {
                FMA2(acc2[oi][0], wb[oi], x4.u[0], acc2[oi][0]);
                FMA2(acc2[oi][1], wb[oi], x4.u[1], acc2[oi][1]);
            }
        }
        __syncthreads();
    }

    float vals[4][4];
#pragma unroll
    for (int oi = 0; oi < 4; oi++) {
        vals[oi][0] = lo_f(acc2[oi][0]); vals[oi][1] = hi_f(acc2[oi][0]);
        vals[oi][2] = lo_f(acc2[oi][1]); vals[oi][3] = hi_f(acc2[oi][1]);
    }

    if (DST == DST_Q || DST == DST_K) {
        if (o0 < DQK) {
            uint32_t* gh = ((DST == DST_Q) ? g_qh : g_kh) + (size_t)b * NTOK * 16;
            uint32_t* gl = ((DST == DST_Q) ? g_ql : g_kl) + (size_t)b * NTOK * 16;
            float bv[4] = {bias[o0], bias[o0 + 1], bias[o0 + 2], bias[o0 + 3]};
#pragma unroll
            for (int ni = 0; ni < 4; ni++) {
                float h[4], l[4];
#pragma unroll
                for (int oi = 0; oi < 4; oi++) bsp(vals[oi][ni] + bv[oi], h[oi], l[oi]);
                size_t widx = (size_t)(ntile + n0 + ni) * 16 + (o0 >> 1);
                *(uint2*)(gh + widx) = make_uint2(pk2(h[0], h[1]), pk2(h[2], h[3]));
                *(uint2*)(gl + widx) = make_uint2(pk2(l[0], l[1]), pk2(l[2], l[3]));
            }
        }
    } else if (DST == DST_V) {
#pragma unroll
        for (int oi = 0; oi < 4; oi++) {
            int o = otile + o0 + oi;
            float bv = bias[o];
            float h[4], l[4];
#pragma unroll
            for (int ni = 0; ni < 4; ni++) bsp(vals[oi][ni] + bv, h[ni], l[ni]);
            size_t widx = ((size_t)b * CCH + o) * (NTOK / 2) + ((ntile + n0) >> 1);
            *(uint2*)(g_vh + widx) = make_uint2(pk2(h[0], h[1]), pk2(h[2], h[3]));
            *(uint2*)(g_vl + widx) = make_uint2(pk2(l[0], l[1]), pk2(l[2], l[3]));
        }
    } else {
        float* ob = outparam + (size_t)b * OC * NTOK;
        const float* rb = xparam + (size_t)b * OC * NTOK;
#pragma unroll
        for (int oi = 0; oi < 4; oi++) {
            int o = otile + o0 + oi;
            float bv = bias[o];
            size_t off = (size_t)o * NTOK + ntile + n0;
            float4 r;
            r.x = vals[oi][0] + bv; r.y = vals[oi][1] + bv;
            r.z = vals[oi][2] + bv; r.w = vals[oi][3] + bv;
            if (RES) {
                float4 rr = *(const float4*)&rb[off];
                r.x += rr.x; r.y += rr.y; r.z += rr.z; r.w += rr.w;
            }
            *(float4*)&ob[off] = r;
        }
    }
}

// ---------------------------------------------------------------------------
// mma.sync / ldmatrix / cp.async helpers
// ---------------------------------------------------------------------------
__device__ __forceinline__ uint32_t smem_u32(const void* p) {
    uint32_t a;
    asm("{ .reg .u64 t; cvta.to.shared.u64 t, %1; cvt.u32.u64 %0, t; }"
        : "=r"(a) : "l"(p));
    return a;
}
__device__ __forceinline__ void ldsm4(uint32_t addr, uint32_t& r0, uint32_t& r1,
                                      uint32_t& r2, uint32_t& r3) {
    asm volatile("ldmatrix.sync.aligned.m8n8.x4.shared.b16 {%0,%1,%2,%3}, [%4];"
                 : "=r"(r0), "=r"(r1), "=r"(r2), "=r"(r3) : "r"(addr));
}
__device__ __forceinline__ void mmabf(float* d, const uint32_t* a,
                                      uint32_t b0, uint32_t b1) {
    asm volatile(
        "mma.sync.aligned.m16n8k16.row.col.f32.bf16.bf16.f32 "
        "{%0,%1,%2,%3}, {%4,%5,%6,%7}, {%8,%9}, {%0,%1,%2,%3};"
        : "+f"(d[0]), "+f"(d[1]), "+f"(d[2]), "+f"(d[3])
        : "r"(a[0]), "r"(a[1]), "r"(a[2]), "r"(a[3]), "r"(b0), "r"(b1));
}
__device__ __forceinline__ void cp16(uint32_t dst, const void* src) {
    asm volatile("cp.async.cg.shared.global [%0], [%1], 16;"
                 :: "r"(dst), "l"(src) : "memory");
}
#define CP_COMMIT() asm volatile("cp.async.commit_group;" ::: "memory")
#define CP_WAIT1()  asm volatile("cp.async.wait_group 1;" ::: "memory")

// ---------------------------------------------------------------------------
// Attention SMEM layout (bytes):
//   QH 0, QL 10240          (128 rows x 80B)
//   K buf0 20480, buf1 30720 (64 rows x 80B, hi at +0, lo at +5120)
//   V buf0 40960, buf1 114688 (256 rows x 144B, hi at +0, lo at +36864)
// ---------------------------------------------------------------------------
#define SM_QH 0
#define SM_QL 10240
#define KB0   20480
#define KB1   30720
#define KLOFF 5120
#define VB0   40960
#define VB1   114688
#define VLOFF 36864
#define ATTN_SMEM 188416

__device__ __forceinline__ void issue_tile(uint32_t sb, int buf, int nc, int t,
    const uint4* gkh, const uint4* gkl, const uint4* gvh, const uint4* gvl)
{
    const uint32_t kb = sb + (buf ? KB1 : KB0);
    const uint32_t vb = sb + (buf ? VB1 : VB0);
    const int krow = t >> 2, kq = t & 3;
    cp16(kb + krow * 80 + kq * 16,         gkh + (size_t)(nc + krow) * 4 + kq);
    cp16(kb + KLOFF + krow * 80 + kq * 16, gkl + (size_t)(nc + krow) * 4 + kq);
    const int vr = t >> 3, vq = t & 7;
    const int nq = nc >> 3;
#pragma unroll
    for (int i = 0; i < 8; i++) {
        int row = vr + i * 32;
        cp16(vb + row * 144 + vq * 16,         gvh + (size_t)row * 512 + nq + vq);
        cp16(vb + VLOFF + row * 144 + vq * 16, gvl + (size_t)row * 512 + nq + vq);
    }
}

__global__ __launch_bounds__(256) void attn_mma_kernel()
{
    extern __shared__ __align__(16) char smem[];
    const int t = threadIdx.x, lane = t & 31, w = t >> 5;
    const int b = blockIdx.y, q0 = blockIdx.x * 128;
    const uint32_t sb = smem_u32(smem);

    const uint4* gkh = (const uint4*)g_kh + (size_t)b * NTOK * 4;
    const uint4* gkl = (const uint4*)g_kl + (size_t)b * NTOK * 4;
    const uint4* gvh = (const uint4*)g_vh + (size_t)b * CCH * 512;
    const uint4* gvl = (const uint4*)g_vl + (size_t)b * CCH * 512;

    // ---- Q tile -> SMEM (hi/lo), once ----
    {
        int row = t >> 1;
        size_t gidx = ((size_t)b * NTOK + q0 + row) * 4 + (t & 1) * 2;
        const uint4* sh = (const uint4*)g_qh + gidx;
        const uint4* sl = (const uint4*)g_ql + gidx;
        uint4* dh = (uint4*)(smem + SM_QH + row * 80 + (t & 1) * 32);
        uint4* dl = (uint4*)(smem + SM_QL + row * 80 + (t & 1) * 32);
        dh[0] = sh[0]; dh[1] = sh[1];
        dl[0] = sl[0]; dl[1] = sl[1];
    }
    // prologue: issue tile 0 while Q settles
    issue_tile(sb, 0, 0, t, gkh, gkl, gvh, gvl);
    CP_COMMIT();
    __syncthreads();

    // ---- preload Q A-fragments ----
    const int a_row  = (lane & 7) + (lane & 8);
    const int a_kofs = (lane & 16) ? 8 : 0;
    const int b_row  = (lane & 7) + ((lane & 16) ? 8 : 0);
    const int b_kofs = (lane & 8);

    uint32_t qa_h[2][4], qa_l[2][4];
#pragma unroll
    for (int kc = 0; kc < 2; kc++) {
        uint32_t byteoff = (uint32_t)(w * 16 + a_row) * 80 + (kc * 16 + a_kofs) * 2;
        ldsm4(sb + SM_QH + byteoff, qa_h[kc][0], qa_h[kc][1], qa_h[kc][2], qa_h[kc][3]);
        ldsm4(sb + SM_QL + byteoff, qa_l[kc][0], qa_l[kc][1], qa_l[kc][2], qa_l[kc][3]);
    }

    float M0 = -1e30f, M1 = -1e30f, sum0 = 0.f, sum1 = 0.f;
    float o[32][4];
#pragma unroll
    for (int i = 0; i < 32; i++)
#pragma unroll
        for (int j = 0; j < 4; j++) o[i][j] = 0.f;

    // ================= single-pass online flash loop =================
    for (int ti = 0; ti < 64; ti++) {
        if (ti < 63) issue_tile(sb, (ti + 1) & 1, (ti + 1) * 64, t, gkh, gkl, gvh, gvl);
        CP_COMMIT();
        CP_WAIT1();
        __syncthreads();

        const uint32_t kb = sb + ((ti & 1) ? KB1 : KB0);
        const uint32_t vb = sb + ((ti & 1) ? VB1 : VB0);

        // ---- S = Q.K^T (3-term) ----
        float sfr[8][4];
#pragma unroll
        for (int i = 0; i < 8; i++)
#pragma unroll
            for (int j = 0; j < 4; j++) sfr[i][j] = 0.f;

#pragma unroll
        for (int nfp = 0; nfp < 4; nfp++)
#pragma unroll
            for (int kc = 0; kc < 2; kc++) {
                uint32_t boff = (uint32_t)(nfp * 16 + b_row) * 80 + (kc * 16 + b_kofs) * 2;
                uint32_t h0, h1, h2, h3, l0, l1, l2, l3;
                ldsm4(kb + boff, h0, h1, h2, h3);
                ldsm4(kb + KLOFF + boff, l0, l1, l2, l3);
                mmabf(sfr[2 * nfp],     qa_h[kc], h0, h1);
                mmabf(sfr[2 * nfp + 1], qa_h[kc], h2, h3);
                mmabf(sfr[2 * nfp],     qa_h[kc], l0, l1);
                mmabf(sfr[2 * nfp + 1], qa_h[kc], l2, l3);
                mmabf(sfr[2 * nfp],     qa_l[kc], h0, h1);
                mmabf(sfr[2 * nfp + 1], qa_l[kc], h2, h3);
            }

        // ---- online max update ----
        float tm0 = -1e30f, tm1 = -1e30f;
#pragma unroll
        for (int nf = 0; nf < 8; nf++) {
            tm0 = fmaxf(tm0, fmaxf(sfr[nf][0], sfr[nf][1]));
            tm1 = fmaxf(tm1, fmaxf(sfr[nf][2], sfr[nf][3]));
        }
        tm0 = fmaxf(tm0, __shfl_xor_sync(0xffffffffu, tm0, 1));
        tm0 = fmaxf(tm0, __shfl_xor_sync(0xffffffffu, tm0, 2));
        tm1 = fmaxf(tm1, __shfl_xor_sync(0xffffffffu, tm1, 1));
        tm1 = fmaxf(tm1, __shfl_xor_sync(0xffffffffu, tm1, 2));
        float nM0 = fmaxf(M0, tm0), nM1 = fmaxf(M1, tm1);
        float sc0 = __expf(M0 - nM0), sc1 = __expf(M1 - nM1);
        M0 = nM0; M1 = nM1;
        sum0 *= sc0; sum1 *= sc1;
#pragma unroll
        for (int nf = 0; nf < 32; nf++) {
            o[nf][0] *= sc0; o[nf][1] *= sc0;
            o[nf][2] *= sc1; o[nf][3] *= sc1;
        }

        // ---- P = exp(S - M), pack bf16 hi/lo A-fragments ----
        uint32_t pah[4][4], pal[4][4];
#pragma unroll
        for (int kc = 0; kc < 4; kc++) {
            int fa = 2 * kc, fb = 2 * kc + 1;
            float p[8];
            p[0] = __expf(sfr[fa][0] - M0); p[1] = __expf(sfr[fa][1] - M0);
            p[2] = __expf(sfr[fa][2] - M1); p[3] = __expf(sfr[fa][3] - M1);
            p[4] = __expf(sfr[fb][0] - M0); p[5] = __expf(sfr[fb][1] - M0);
            p[6] = __expf(sfr[fb][2] - M1); p[7] = __expf(sfr[fb][3] - M1);
            sum0 += p[0] + p[1] + p[4] + p[5];
            sum1 += p[2] + p[3] + p[6] + p[7];
            float h[8], l[8];
#pragma unroll
            for (int i = 0; i < 8; i++) bsp(p[i], h[i], l[i]);
            pah[kc][0] = pk2(h[0], h[1]); pah[kc][1] = pk2(h[2], h[3]);
            pah[kc][2] = pk2(h[4], h[5]); pah[kc][3] = pk2(h[6], h[7]);
            pal[kc][0] = pk2(l[0], l[1]); pal[kc][1] = pk2(l[2], l[3]);
            pal[kc][2] = pk2(l[4], l[5]); pal[kc][3] = pk2(l[6], l[7]);
        }

        // ---- O += P.V^T (3-term) ----
#pragma unroll
        for (int nfp = 0; nfp < 16; nfp++)
#pragma unroll
            for (int kc = 0; kc < 4; kc++) {
                uint32_t boff = (uint32_t)(nfp * 16 + b_row) * 144 + (kc * 16 + b_kofs) * 2;
                uint32_t h0, h1, h2, h3, l0, l1, l2, l3;
                ldsm4(vb + boff, h0, h1, h2, h3);
                ldsm4(vb + VLOFF + boff, l0, l1, l2, l3);
                mmabf(o[2 * nfp],     pah[kc], h0, h1);
                mmabf(o[2 * nfp + 1], pah[kc], h2, h3);
                mmabf(o[2 * nfp],     pah[kc], l0, l1);
                mmabf(o[2 * nfp + 1], pah[kc], l2, l3);
                mmabf(o[2 * nfp],     pal[kc], h0, h1);
                mmabf(o[2 * nfp + 1], pal[kc], h2, h3);
            }
        __syncthreads();
    }

    sum0 += __shfl_xor_sync(0xffffffffu, sum0, 1);
    sum0 += __shfl_xor_sync(0xffffffffu, sum0, 2);
    sum1 += __shfl_xor_sync(0xffffffffu, sum1, 1);
    sum1 += __shfl_xor_sync(0xffffffffu, sum1, 2);
    const float inv0 = 1.f / sum0, inv1 = 1.f / sum1;

    // ---- epilogue: O/sum -> g_ao[b][c][n] ----
    {
        float* aob = g_ao + (size_t)b * CCH * NTOK;
        const int r = lane >> 2, qd = lane & 3;
        const int n_g = q0 + w * 16 + r;
#pragma unroll
        for (int nf = 0; nf < 32; nf++) {
            int c0 = nf * 8 + qd * 2;
            aob[(size_t)c0 * NTOK + n_g]           = o[nf][0] * inv0;
            aob[(size_t)(c0 + 1) * NTOK + n_g]     = o[nf][1] * inv0;
            aob[(size_t)c0 * NTOK + n_g + 8]       = o[nf][2] * inv1;
            aob[(size_t)(c0 + 1) * NTOK + n_g + 8] = o[nf][3] * inv1;
        }
    }
}

// ---------------------------------------------------------------------------

extern "C" void kernel_launch(void* const* d_in, const int* in_sizes, int n_in,
                              void* d_out, int out_size)
{
    const float* x  = (const float*)d_in[0];
    const float* wq = (const float*)d_in[1];
    const float* bq = (const float*)d_in[2];
    const float* wk = (const float*)d_in[3];
    const float* bk = (const float*)d_in[4];
    const float* wv = (const float*)d_in[5];
    const float* bv = (const float*)d_in[6];
    const float* wo = (const float*)d_in[7];
    const float* bo = (const float*)d_in[8];
    float* out = (float*)d_out;

    cudaFuncSetAttribute(attn_mma_kernel, cudaFuncAttributeMaxDynamicSharedMemorySize,
                         ATTN_SMEM);

    dim3 blk(256);
    proj_kernel<DQK, DST_Q,  false><<<dim3(NTOK / 64, 1, BATCH), blk>>>(x, wq, bq, nullptr);
    proj_kernel<DQK, DST_K,  false><<<dim3(NTOK / 64, 1, BATCH), blk>>>(x, wk, bk, nullptr);
    proj_kernel<CCH, DST_V,  false><<<dim3(NTOK / 64, CCH / 64, BATCH), blk>>>(x, wv, bv, nullptr);
    attn_mma_kernel<<<dim3(NTOK / 128, BATCH), blk, ATTN_SMEM>>>();
    proj_kernel<CCH, DST_OUT, true><<<dim3(NTOK / 64, CCH / 64, BATCH), blk>>>(x, wo, bo, out);
}